// round 8
// baseline (speedup 1.0000x reference)
#include <cuda_runtime.h>
#include <cuda_bf16.h>
#include <cstdint>
#include <cstddef>

static constexpr int B_  = 4;
static constexpr int N_  = 4096;
static constexpr int F_  = 256;
static constexpr int FO_ = 64;
static constexpr int TM_ = 64;     // t rows per CTA (2 CTAs/SM)

// main smem: EB1 16K | EB2 16K | V single-buf 64K (hi32K+lo32K) | sden 1K
static constexpr int EB1O = 0;
static constexpr int EB2O = 16384;
static constexpr int VO   = 32768;
static constexpr int SDEN = 98304;
static constexpr int SMEM_MAIN = 99584;

static constexpr int K2_CS_STRIDE = 66;
static constexpr int K2_WS_OFF = 64 * K2_CS_STRIDE * 4;      // 16896
static constexpr int K2_SMEM  = K2_WS_OFF + 64 * 64 * 4;     // 33280

__device__ float g_EA1[B_ * N_];
__device__ float g_EA2[B_ * N_];
__device__ float g_EB1[B_ * N_];
__device__ float g_EB2[B_ * N_];
__device__ __nv_bfloat16 g_Vhi[(size_t)B_ * N_ * FO_];
__device__ __nv_bfloat16 g_Vlo[(size_t)B_ * N_ * FO_];

__device__ __forceinline__ uint32_t smem_u32(const void* p) {
    uint32_t a;
    asm("{ .reg .u64 t; cvta.to.shared.u64 t, %1; cvt.u32.u64 %0, t; }" : "=r"(a) : "l"(p));
    return a;
}
__device__ __forceinline__ uint32_t pack_hi(float a, float b) {
    uint32_t r;
    asm("prmt.b32 %0, %1, %2, 0x7632;" : "=r"(r)
        : "r"(__float_as_uint(a)), "r"(__float_as_uint(b)));
    return r;
}
__device__ __forceinline__ uint32_t pack_rn(float a, float b) {
    uint32_t r;
    asm("cvt.rn.bf16x2.f32 %0, %1, %2;" : "=r"(r) : "f"(b), "f"(a));
    return r;
}
__device__ __forceinline__ float trunc_bf16(float a) {
    return __uint_as_float(__float_as_uint(a) & 0xFFFF0000u);
}
__device__ __forceinline__ void ldsm4t(uint32_t* r, uint32_t addr) {
    asm volatile("ldmatrix.sync.aligned.m8n8.x4.trans.shared.b16 {%0,%1,%2,%3}, [%4];"
        : "=r"(r[0]), "=r"(r[1]), "=r"(r[2]), "=r"(r[3]) : "r"(addr));
}
__device__ __forceinline__ void mma16816(float* c, uint32_t a0, uint32_t a1, uint32_t a2, uint32_t a3,
                                         uint32_t b0, uint32_t b1) {
    asm volatile("mma.sync.aligned.m16n8k16.row.col.f32.bf16.bf16.f32 "
        "{%0,%1,%2,%3}, {%4,%5,%6,%7}, {%8,%9}, {%0,%1,%2,%3};"
        : "+f"(c[0]), "+f"(c[1]), "+f"(c[2]), "+f"(c[3])
        : "r"(a0), "r"(a1), "r"(a2), "r"(a3), "r"(b0), "r"(b1));
}
__device__ __forceinline__ void cp16(uint32_t dst, const void* src) {
    asm volatile("cp.async.cg.shared.global [%0], [%1], 16;" :: "r"(dst), "l"(src) : "memory");
}
__device__ __forceinline__ void cp_commit() { asm volatile("cp.async.commit_group;" ::: "memory"); }
template <int NW>
__device__ __forceinline__ void cp_wait() { asm volatile("cp.async.wait_group %0;" :: "n"(NW) : "memory"); }

// ---------------- K2: V (hi/lo) + EA   (grid 256, 64 rows/block) ----------------
__global__ __launch_bounds__(256) void gat_k2(const float* __restrict__ ctx,
                                              const float* __restrict__ Ws,
                                              const float* __restrict__ a) {
    extern __shared__ char sm[];
    float* cs  = (float*)sm;                 // [64][stride 66]
    float* wss = (float*)(sm + K2_WS_OFF);   // [64][64]
    int tid = threadIdx.x;
    int g0 = blockIdx.x * 64;
    int rowT = tid >> 4, colT = tid & 15;    // 16 row-tiles x 16 col-tiles
    int r0 = rowT * 4, n0 = colT * 4;
    float acc[4][4];
    #pragma unroll
    for (int i = 0; i < 4; i++)
        #pragma unroll
        for (int c = 0; c < 4; c++) acc[i][c] = 0.f;

    for (int ch = 0; ch < 4; ch++) {
        int fc = ch * 64;
        if (ch) __syncthreads();
        #pragma unroll
        for (int it = 0; it < 4; it++) {
            int lin = tid + it * 256;
            int f4 = lin & 15, r = lin >> 4;
            float4 v = *(const float4*)&ctx[(size_t)(g0 + r) * F_ + fc + f4 * 4];
            float* d = &cs[r * K2_CS_STRIDE + f4 * 4];
            d[0] = v.x; d[1] = v.y; d[2] = v.z; d[3] = v.w;
        }
        #pragma unroll
        for (int it = 0; it < 4; it++) {
            int lin = tid + it * 256;
            int n4 = lin & 15, f = lin >> 4;
            float4 v = *(const float4*)&Ws[(size_t)(fc + f) * FO_ + n4 * 4];
            *(float4*)&wss[f * FO_ + n4 * 4] = v;
        }
        __syncthreads();
        #pragma unroll 4
        for (int f = 0; f < 64; f++) {
            float4 w = *(const float4*)&wss[f * FO_ + n0];
            #pragma unroll
            for (int i = 0; i < 4; i++) {
                float c = cs[(r0 + i) * K2_CS_STRIDE + f];
                acc[i][0] += c * w.x; acc[i][1] += c * w.y;
                acc[i][2] += c * w.z; acc[i][3] += c * w.w;
            }
        }
    }
    __syncthreads();
    float a1c[4];
    #pragma unroll
    for (int c = 0; c < 4; c++) a1c[c] = a[n0 + c];
    float* red = (float*)sm;  // [64][16]
    #pragma unroll
    for (int i = 0; i < 4; i++) {
        float part = acc[i][0] * a1c[0] + acc[i][1] * a1c[1]
                   + acc[i][2] * a1c[2] + acc[i][3] * a1c[3];
        float l0 = acc[i][0] - trunc_bf16(acc[i][0]);
        float l1 = acc[i][1] - trunc_bf16(acc[i][1]);
        float l2 = acc[i][2] - trunc_bf16(acc[i][2]);
        float l3 = acc[i][3] - trunc_bf16(acc[i][3]);
        uint2 hst = make_uint2(pack_hi(acc[i][0], acc[i][1]), pack_hi(acc[i][2], acc[i][3]));
        uint2 lst = make_uint2(pack_rn(l0, l1), pack_rn(l2, l3));
        size_t base = (size_t)(g0 + r0 + i) * FO_ + n0;
        *(uint2*)&g_Vhi[base] = hst;
        *(uint2*)&g_Vlo[base] = lst;
        red[(r0 + i) * 16 + colT] = part;
    }
    __syncthreads();
    if (tid < 64) {
        float s = 0.f;
        #pragma unroll
        for (int j = 0; j < 16; j++) s += red[tid * 16 + j];
        g_EA1[g0 + tid] = __expf(s);
        g_EA2[g0 + tid] = __expf(0.2f * s);
    }
}

// ---------------- K3: EB (w2 inline), grid 256 x 64 rows ----------------
__global__ __launch_bounds__(256) void gat_k3(const float* __restrict__ h,
                                              const float* __restrict__ Wt,
                                              const float* __restrict__ a) {
    __shared__ float w2s[F_];
    int tid = threadIdx.x;
    {
        float acc = 0.f;
        const float* wr = Wt + (size_t)tid * FO_;
        #pragma unroll 8
        for (int o = 0; o < FO_; o++) acc += wr[o] * a[FO_ + o];
        w2s[tid] = acc;
    }
    __syncthreads();
    int lane = tid & 31, w = tid >> 5;
    int rb = blockIdx.x * 64;
    const float4* wp = (const float4*)w2s;
    float4 w0 = wp[lane], w1 = wp[lane + 32];
    #pragma unroll
    for (int it = 0; it < 8; it++) {
        int sg = rb + it * 8 + w;
        const float4* hp = (const float4*)(h + (size_t)sg * F_);
        float4 x0 = hp[lane], x1 = hp[lane + 32];
        float d = x0.x * w0.x + x0.y * w0.y + x0.z * w0.z + x0.w * w0.w
                + x1.x * w1.x + x1.y * w1.y + x1.z * w1.z + x1.w * w1.w;
        #pragma unroll
        for (int off = 16; off > 0; off >>= 1) d += __shfl_xor_sync(0xffffffffu, d, off);
        if (lane == 0) {
            g_EB1[sg] = __expf(d);
            g_EB2[sg] = __expf(0.2f * d);
        }
    }
}

// ---------------- main: 2 M-warps x 4 K-quarter warps, 2 CTAs/SM ----------------
__global__ __launch_bounds__(256, 2)
void gat_main(const int* __restrict__ adj, float* __restrict__ out) {
    extern __shared__ char sm[];
    uint32_t smb = smem_u32(sm);
    float* EB1s = (float*)(sm + EB1O);
    float* EB2s = (float*)(sm + EB2O);
    float* sden = (float*)(sm + SDEN);   // [4][64]

    int tid = threadIdx.x;
    int l = tid & 31, wid = tid >> 5;
    int cta = blockIdx.x;
    int b = cta >> 6;
    int t0 = (cta & 63) * TM_;
    int bN = b * N_;
    int wm = wid & 1;    // rows wm*32 .. wm*32+31
    int kh = wid >> 1;   // 64-s quarter within each 256-s super-block

    {
        const float4* s1 = (const float4*)(g_EB1 + bN);
        const float4* s2 = (const float4*)(g_EB2 + bN);
        float4* d1 = (float4*)EB1s;
        float4* d2 = (float4*)EB2s;
        #pragma unroll
        for (int it = 0; it < 4; it++) {
            d1[tid + it * 256] = s1[tid + it * 256];
            d2[tid + it * 256] = s2[tid + it * 256];
        }
    }

    int r0 = wm * 32 + (l >> 2);
    int cb = (l & 3) * 2;
    float ea1[4], ea2[4];
    #pragma unroll
    for (int p = 0; p < 4; p++) {
        ea1[p] = g_EA1[bN + t0 + r0 + p * 8];
        ea2[p] = g_EA2[bN + t0 + r0 + p * 8];
    }
    const int* adjB = adj + (size_t)(bN + t0 + r0) * N_;

    // cp.async V mapping: thread -> rows (tid>>3)+32*rho, 16B chunk (tid&7)
    int vr = tid >> 3, vc = tid & 7;
    uint32_t vdsw = (uint32_t)((vr * 128 + vc * 16) ^ ((vr & 7) << 4));
    const char* vsh = (const char*)(g_Vhi + ((size_t)bN + vr) * FO_ + vc * 8);
    const char* vsl = (const char*)(g_Vlo + ((size_t)bN + vr) * FO_ + vc * 8);

    uint32_t lb = (uint32_t)((kh * 64 + (l & 15)) * 128 + (l >> 4) * 16);
    uint32_t swx = (uint32_t)((l & 7) << 4);

    // prologue: V super-block 0 (hi 32K at VO, lo 32K at VO+32768; 32 rows per rho step)
    {
        uint32_t d = smb + VO + vdsw;
        #pragma unroll
        for (int rho = 0; rho < 8; rho++) {
            cp16(d + rho * 4096, vsh + rho * 4096);
            cp16(d + 32768 + rho * 4096, vsl + rho * 4096);
        }
        cp_commit();
    }
    // adj prefetch (j=0, kk=0)
    int2 ajn[8];
    {
        int c0 = kh * 64 + cb;
        #pragma unroll
        for (int p = 0; p < 4; p++) {
            ajn[2 * p]     = *(const int2*)(adjB + (size_t)p * 8 * N_ + c0);
            ajn[2 * p + 1] = *(const int2*)(adjB + (size_t)p * 8 * N_ + c0 + 8);
        }
    }

    float C0[8][4], C1[8][4];
    #pragma unroll
    for (int f = 0; f < 8; f++)
        #pragma unroll
        for (int i = 0; i < 4; i++) { C0[f][i] = 0.f; C1[f][i] = 0.f; }
    float dden[4] = {0.f, 0.f, 0.f, 0.f};

    uint32_t vbhi = smb + VO;
    uint32_t vblo = vbhi + 32768;

    for (int j = 0; j < 16; j++) {
        cp_wait<0>();
        __syncthreads();
        int sj = j * 256 + kh * 64;

        #pragma unroll
        for (int kk = 0; kk < 4; kk++) {
            int c0 = sj + kk * 16 + cb;
            float2 e1a = *(const float2*)&EB1s[c0];
            float2 e1b = *(const float2*)&EB1s[c0 + 8];
            float2 e2a = *(const float2*)&EB2s[c0];
            float2 e2b = *(const float2*)&EB2s[c0 + 8];

            uint32_t hA[4], hB[4], lA[4], lB[4];
            #pragma unroll
            for (int p = 0; p < 4; p++) {
                int2 A0 = ajn[2 * p], A1 = ajn[2 * p + 1];
                float p1, p2, x0, x1, x2, x3;
                p1 = ea1[p] * e1a.x; p2 = ea2[p] * e2a.x; x0 = (p1 > 1.f) ? p1 : p2; x0 = (A0.x > 0) ? x0 : 0.f;
                p1 = ea1[p] * e1a.y; p2 = ea2[p] * e2a.y; x1 = (p1 > 1.f) ? p1 : p2; x1 = (A0.y > 0) ? x1 : 0.f;
                p1 = ea1[p] * e1b.x; p2 = ea2[p] * e2b.x; x2 = (p1 > 1.f) ? p1 : p2; x2 = (A1.x > 0) ? x2 : 0.f;
                p1 = ea1[p] * e1b.y; p2 = ea2[p] * e2b.y; x3 = (p1 > 1.f) ? p1 : p2; x3 = (A1.y > 0) ? x3 : 0.f;
                dden[p] += (x0 + x1) + (x2 + x3);
                hA[p] = pack_hi(x0, x1);
                lA[p] = pack_rn(x0 - trunc_bf16(x0), x1 - trunc_bf16(x1));
                hB[p] = pack_hi(x2, x3);
                lB[p] = pack_rn(x2 - trunc_bf16(x2), x3 - trunc_bf16(x3));
            }
            // prefetch adj for next kk (or next super-block)
            {
                int cn = (kk < 3) ? (c0 + 16) : ((j < 15) ? (c0 + 208) : c0);
                #pragma unroll
                for (int p = 0; p < 4; p++) {
                    ajn[2 * p]     = *(const int2*)(adjB + (size_t)p * 8 * N_ + cn);
                    ajn[2 * p + 1] = *(const int2*)(adjB + (size_t)p * 8 * N_ + cn + 8);
                }
            }
            uint32_t ob = lb + (uint32_t)(kk * 2048);
            #pragma unroll
            for (int ng = 0; ng < 4; ng++) {
                uint32_t off = (ob + (uint32_t)(ng * 32)) ^ swx;
                uint32_t bh[4], bl[4];
                ldsm4t(bh, vbhi + off);
                ldsm4t(bl, vblo + off);
                mma16816(C0[2 * ng],     hA[0], hA[1], hB[0], hB[1], bh[0], bh[1]);
                mma16816(C1[2 * ng],     hA[2], hA[3], hB[2], hB[3], bh[0], bh[1]);
                mma16816(C0[2 * ng + 1], hA[0], hA[1], hB[0], hB[1], bh[2], bh[3]);
                mma16816(C1[2 * ng + 1], hA[2], hA[3], hB[2], hB[3], bh[2], bh[3]);
                mma16816(C0[2 * ng],     lA[0], lA[1], lB[0], lB[1], bh[0], bh[1]);
                mma16816(C1[2 * ng],     lA[2], lA[3], lB[2], lB[3], bh[0], bh[1]);
                mma16816(C0[2 * ng + 1], lA[0], lA[1], lB[0], lB[1], bh[2], bh[3]);
                mma16816(C1[2 * ng + 1], lA[2], lA[3], lB[2], lB[3], bh[2], bh[3]);
                mma16816(C0[2 * ng],     hA[0], hA[1], hB[0], hB[1], bl[0], bl[1]);
                mma16816(C1[2 * ng],     hA[2], hA[3], hB[2], hB[3], bl[0], bl[1]);
                mma16816(C0[2 * ng + 1], hA[0], hA[1], hB[0], hB[1], bl[2], bl[3]);
                mma16816(C1[2 * ng + 1], hA[2], hA[3], hB[2], hB[3], bl[2], bl[3]);
            }
        }
        __syncthreads();
        if (j < 15) {
            uint32_t d = smb + VO + vdsw;
            const char* sh = vsh + (size_t)(j + 1) * 32768;
            const char* sl = vsl + (size_t)(j + 1) * 32768;
            #pragma unroll
            for (int rho = 0; rho < 8; rho++) {
                cp16(d + rho * 4096, sh + rho * 4096);
                cp16(d + 32768 + rho * 4096, sl + rho * 4096);
            }
            cp_commit();
        }
    }

    // ---- epilogue ----
    #pragma unroll
    for (int p = 0; p < 4; p++) {
        dden[p] += __shfl_xor_sync(0xffffffffu, dden[p], 1);
        dden[p] += __shfl_xor_sync(0xffffffffu, dden[p], 2);
    }
    if ((l & 3) == 0) {
        #pragma unroll
        for (int p = 0; p < 4; p++) sden[kh * 64 + r0 + p * 8] = dden[p];
    }
    // kh=1..3 dump partials into V area: [kh-1][row(64)][64] floats
    if (kh) {
        float* mb = (float*)(sm + VO) + (size_t)(kh - 1) * 4096;
        #pragma unroll
        for (int g = 0; g < 2; g++) {
            int rr = wm * 32 + g * 16 + (l >> 2);
            float (*Cg)[4] = g ? C1 : C0;
            #pragma unroll
            for (int f = 0; f < 8; f++) {
                *(float2*)&mb[rr * 64 + f * 8 + cb]       = make_float2(Cg[f][0], Cg[f][1]);
                *(float2*)&mb[(rr + 8) * 64 + f * 8 + cb] = make_float2(Cg[f][2], Cg[f][3]);
            }
        }
    }
    __syncthreads();
    if (kh == 0) {
        const float* m1 = (const float*)(sm + VO);
        const float* m2 = m1 + 4096;
        const float* m3 = m2 + 4096;
        #pragma unroll
        for (int g = 0; g < 2; g++) {
            int rr = wm * 32 + g * 16 + (l >> 2);
            float rd0 = 1.f / (sden[rr] + sden[64 + rr] + sden[128 + rr] + sden[192 + rr]);
            int rs = rr + 8;
            float rd1 = 1.f / (sden[rs] + sden[64 + rs] + sden[128 + rs] + sden[192 + rs]);
            float (*Cg)[4] = g ? C1 : C0;
            float* o0 = out + (size_t)(bN + t0 + rr) * FO_ + cb;
            float* o1 = out + (size_t)(bN + t0 + rs) * FO_ + cb;
            #pragma unroll
            for (int f = 0; f < 8; f++) {
                int i0 = rr * 64 + f * 8 + cb, i1 = rs * 64 + f * 8 + cb;
                float x0 = (Cg[f][0] + m1[i0] + m2[i0] + m3[i0]) * rd0;
                float x1 = (Cg[f][1] + m1[i0 + 1] + m2[i0 + 1] + m3[i0 + 1]) * rd0;
                float x2 = (Cg[f][2] + m1[i1] + m2[i1] + m3[i1]) * rd1;
                float x3 = (Cg[f][3] + m1[i1 + 1] + m2[i1 + 1] + m3[i1 + 1]) * rd1;
                x0 = (x0 > 0.f) ? x0 : 0.01f * x0;
                x1 = (x1 > 0.f) ? x1 : 0.01f * x1;
                x2 = (x2 > 0.f) ? x2 : 0.01f * x2;
                x3 = (x3 > 0.f) ? x3 : 0.01f * x3;
                *(float2*)o0 = make_float2(x0, x1);
                *(float2*)o1 = make_float2(x2, x3);
                o0 += 8; o1 += 8;
            }
        }
    }
}

// ---------------- launcher ----------------
extern "C" void kernel_launch(void* const* d_in, const int* in_sizes, int n_in,
                              void* d_out, int out_size) {
    const float* h   = (const float*)d_in[0];
    const float* ctx = (const float*)d_in[1];
    const int*   adj = (const int*)d_in[2];
    const float* Ws  = (const float*)d_in[3];
    const float* Wt  = (const float*)d_in[4];
    const float* a   = (const float*)d_in[5];
    float* out = (float*)d_out;

    cudaFuncSetAttribute(gat_k2, cudaFuncAttributeMaxDynamicSharedMemorySize, K2_SMEM);
    cudaFuncSetAttribute(gat_main, cudaFuncAttributeMaxDynamicSharedMemorySize, SMEM_MAIN);

    gat_k2<<<(B_ * N_) / 64, 256, K2_SMEM>>>(ctx, Ws, a);
    gat_k3<<<(B_ * N_) / 64, 256>>>(h, Wt, a);
    gat_main<<<B_ * (N_ / TM_), 256, SMEM_MAIN>>>(adj, out);
}

// round 9
// speedup vs baseline: 1.0407x; 1.0407x over previous
#include <cuda_runtime.h>
#include <cuda_bf16.h>
#include <cstdint>
#include <cstddef>

static constexpr int B_  = 4;
static constexpr int N_  = 4096;
static constexpr int F_  = 256;
static constexpr int FO_ = 64;
static constexpr int TM_ = 64;     // t rows per CTA (2 CTAs/SM)

// main smem: EB1 16K | EB2 16K | V dbl-buf 2x32K (hi16K+lo16K) | sden 1K
static constexpr int EB1O = 0;
static constexpr int EB2O = 16384;
static constexpr int VO   = 32768;
static constexpr int SDEN = 98304;
static constexpr int SMEM_MAIN = 99584;

static constexpr int K2_CS_STRIDE = 66;
static constexpr int K2_WS_OFF = 64 * K2_CS_STRIDE * 4;      // 16896
static constexpr int K2_SMEM  = K2_WS_OFF + 64 * 64 * 4;     // 33280

__device__ float g_EA1[B_ * N_];
__device__ float g_EA2[B_ * N_];
__device__ float g_EB1[B_ * N_];
__device__ float g_EB2[B_ * N_];
__device__ __nv_bfloat16 g_Vhi[(size_t)B_ * N_ * FO_];
__device__ __nv_bfloat16 g_Vlo[(size_t)B_ * N_ * FO_];

__device__ __forceinline__ uint32_t smem_u32(const void* p) {
    uint32_t a;
    asm("{ .reg .u64 t; cvta.to.shared.u64 t, %1; cvt.u32.u64 %0, t; }" : "=r"(a) : "l"(p));
    return a;
}
__device__ __forceinline__ uint32_t pack_hi(float a, float b) {
    uint32_t r;
    asm("prmt.b32 %0, %1, %2, 0x7632;" : "=r"(r)
        : "r"(__float_as_uint(a)), "r"(__float_as_uint(b)));
    return r;
}
__device__ __forceinline__ uint32_t pack_rn(float a, float b) {
    uint32_t r;
    asm("cvt.rn.bf16x2.f32 %0, %1, %2;" : "=r"(r) : "f"(b), "f"(a));
    return r;
}
__device__ __forceinline__ float trunc_bf16(float a) {
    return __uint_as_float(__float_as_uint(a) & 0xFFFF0000u);
}
__device__ __forceinline__ void ldsm4t(uint32_t* r, uint32_t addr) {
    asm volatile("ldmatrix.sync.aligned.m8n8.x4.trans.shared.b16 {%0,%1,%2,%3}, [%4];"
        : "=r"(r[0]), "=r"(r[1]), "=r"(r[2]), "=r"(r[3]) : "r"(addr));
}
__device__ __forceinline__ void mma16816(float* c, uint32_t a0, uint32_t a1, uint32_t a2, uint32_t a3,
                                         uint32_t b0, uint32_t b1) {
    asm volatile("mma.sync.aligned.m16n8k16.row.col.f32.bf16.bf16.f32 "
        "{%0,%1,%2,%3}, {%4,%5,%6,%7}, {%8,%9}, {%0,%1,%2,%3};"
        : "+f"(c[0]), "+f"(c[1]), "+f"(c[2]), "+f"(c[3])
        : "r"(a0), "r"(a1), "r"(a2), "r"(a3), "r"(b0), "r"(b1));
}
__device__ __forceinline__ void cp16(uint32_t dst, const void* src) {
    asm volatile("cp.async.cg.shared.global [%0], [%1], 16;" :: "r"(dst), "l"(src) : "memory");
}
__device__ __forceinline__ void cp_commit() { asm volatile("cp.async.commit_group;" ::: "memory"); }
template <int NW>
__device__ __forceinline__ void cp_wait() { asm volatile("cp.async.wait_group %0;" :: "n"(NW) : "memory"); }

// ---------------- K2: V (hi/lo) + EA   (grid 256, 64 rows/block) ----------------
__global__ __launch_bounds__(256) void gat_k2(const float* __restrict__ ctx,
                                              const float* __restrict__ Ws,
                                              const float* __restrict__ a) {
    extern __shared__ char sm[];
    float* cs  = (float*)sm;                 // [64][stride 66]
    float* wss = (float*)(sm + K2_WS_OFF);   // [64][64]
    int tid = threadIdx.x;
    int g0 = blockIdx.x * 64;
    int rowT = tid >> 4, colT = tid & 15;
    int r0 = rowT * 4, n0 = colT * 4;
    float acc[4][4];
    #pragma unroll
    for (int i = 0; i < 4; i++)
        #pragma unroll
        for (int c = 0; c < 4; c++) acc[i][c] = 0.f;

    for (int ch = 0; ch < 4; ch++) {
        int fc = ch * 64;
        if (ch) __syncthreads();
        #pragma unroll
        for (int it = 0; it < 4; it++) {
            int lin = tid + it * 256;
            int f4 = lin & 15, r = lin >> 4;
            float4 v = *(const float4*)&ctx[(size_t)(g0 + r) * F_ + fc + f4 * 4];
            float* d = &cs[r * K2_CS_STRIDE + f4 * 4];
            d[0] = v.x; d[1] = v.y; d[2] = v.z; d[3] = v.w;
        }
        #pragma unroll
        for (int it = 0; it < 4; it++) {
            int lin = tid + it * 256;
            int n4 = lin & 15, f = lin >> 4;
            float4 v = *(const float4*)&Ws[(size_t)(fc + f) * FO_ + n4 * 4];
            *(float4*)&wss[f * FO_ + n4 * 4] = v;
        }
        __syncthreads();
        #pragma unroll 4
        for (int f = 0; f < 64; f++) {
            float4 w = *(const float4*)&wss[f * FO_ + n0];
            #pragma unroll
            for (int i = 0; i < 4; i++) {
                float c = cs[(r0 + i) * K2_CS_STRIDE + f];
                acc[i][0] += c * w.x; acc[i][1] += c * w.y;
                acc[i][2] += c * w.z; acc[i][3] += c * w.w;
            }
        }
    }
    __syncthreads();
    float a1c[4];
    #pragma unroll
    for (int c = 0; c < 4; c++) a1c[c] = a[n0 + c];
    float* red = (float*)sm;  // [64][16]
    #pragma unroll
    for (int i = 0; i < 4; i++) {
        float part = acc[i][0] * a1c[0] + acc[i][1] * a1c[1]
                   + acc[i][2] * a1c[2] + acc[i][3] * a1c[3];
        float l0 = acc[i][0] - trunc_bf16(acc[i][0]);
        float l1 = acc[i][1] - trunc_bf16(acc[i][1]);
        float l2 = acc[i][2] - trunc_bf16(acc[i][2]);
        float l3 = acc[i][3] - trunc_bf16(acc[i][3]);
        uint2 hst = make_uint2(pack_hi(acc[i][0], acc[i][1]), pack_hi(acc[i][2], acc[i][3]));
        uint2 lst = make_uint2(pack_rn(l0, l1), pack_rn(l2, l3));
        size_t base = (size_t)(g0 + r0 + i) * FO_ + n0;
        *(uint2*)&g_Vhi[base] = hst;
        *(uint2*)&g_Vlo[base] = lst;
        red[(r0 + i) * 16 + colT] = part;
    }
    __syncthreads();
    if (tid < 64) {
        float s = 0.f;
        #pragma unroll
        for (int j = 0; j < 16; j++) s += red[tid * 16 + j];
        g_EA1[g0 + tid] = __expf(s);
        g_EA2[g0 + tid] = __expf(0.2f * s);
    }
}

// ---------------- K3: EB (w2 inline), grid 256 x 64 rows ----------------
__global__ __launch_bounds__(256) void gat_k3(const float* __restrict__ h,
                                              const float* __restrict__ Wt,
                                              const float* __restrict__ a) {
    __shared__ float w2s[F_];
    int tid = threadIdx.x;
    {
        float acc = 0.f;
        const float* wr = Wt + (size_t)tid * FO_;
        #pragma unroll 8
        for (int o = 0; o < FO_; o++) acc += wr[o] * a[FO_ + o];
        w2s[tid] = acc;
    }
    __syncthreads();
    int lane = tid & 31, w = tid >> 5;
    int rb = blockIdx.x * 64;
    const float4* wp = (const float4*)w2s;
    float4 w0 = wp[lane], w1 = wp[lane + 32];
    #pragma unroll
    for (int it = 0; it < 8; it++) {
        int sg = rb + it * 8 + w;
        const float4* hp = (const float4*)(h + (size_t)sg * F_);
        float4 x0 = hp[lane], x1 = hp[lane + 32];
        float d = x0.x * w0.x + x0.y * w0.y + x0.z * w0.z + x0.w * w0.w
                + x1.x * w1.x + x1.y * w1.y + x1.z * w1.z + x1.w * w1.w;
        #pragma unroll
        for (int off = 16; off > 0; off >>= 1) d += __shfl_xor_sync(0xffffffffu, d, off);
        if (lane == 0) {
            g_EB1[sg] = __expf(d);
            g_EB2[sg] = __expf(0.2f * d);
        }
    }
}

// ---------------- main: 2 M-warps x 4 K-quarter warps, 2 CTAs/SM, dbl-buf ----------------
__global__ __launch_bounds__(256, 2)
void gat_main(const int* __restrict__ adj, float* __restrict__ out) {
    extern __shared__ char sm[];
    uint32_t smb = smem_u32(sm);
    float* EB1s = (float*)(sm + EB1O);
    float* EB2s = (float*)(sm + EB2O);
    float* sden = (float*)(sm + SDEN);   // [4][64]

    int tid = threadIdx.x;
    int l = tid & 31, wid = tid >> 5;
    int cta = blockIdx.x;
    int b = cta >> 6;
    int t0 = (cta & 63) * TM_;
    int bN = b * N_;
    int wm = wid & 1;    // rows wm*32 .. wm*32+31
    int kh = wid >> 1;   // 32-s quarter within each 128-s super-block

    {
        const float4* s1 = (const float4*)(g_EB1 + bN);
        const float4* s2 = (const float4*)(g_EB2 + bN);
        float4* d1 = (float4*)EB1s;
        float4* d2 = (float4*)EB2s;
        #pragma unroll
        for (int it = 0; it < 4; it++) {
            d1[tid + it * 256] = s1[tid + it * 256];
            d2[tid + it * 256] = s2[tid + it * 256];
        }
    }

    int r0 = wm * 32 + (l >> 2);
    int cb = (l & 3) * 2;
    float ea1[4], ea2[4];
    #pragma unroll
    for (int p = 0; p < 4; p++) {
        ea1[p] = g_EA1[bN + t0 + r0 + p * 8];
        ea2[p] = g_EA2[bN + t0 + r0 + p * 8];
    }
    const int* adjB = adj + (size_t)(bN + t0 + r0) * N_;

    // cp.async V mapping: thread -> rows (tid>>3)+32*rho, 16B chunk (tid&7)
    int vr = tid >> 3, vc = tid & 7;
    uint32_t vdsw = (uint32_t)((vr * 128 + vc * 16) ^ ((vr & 7) << 4));
    const char* vsh = (const char*)(g_Vhi + ((size_t)bN + vr) * FO_ + vc * 8);
    const char* vsl = (const char*)(g_Vlo + ((size_t)bN + vr) * FO_ + vc * 8);

    // ldmatrix geometry: V tile = 128 rows x 128B; row = kh*32 + kk*16 + (l&15)
    uint32_t lb = (uint32_t)((kh * 32 + (l & 15)) * 128 + (l >> 4) * 16);
    uint32_t swx = (uint32_t)((l & 7) << 4);

    // prologue: fill buffer 0 (super-block j=0: 128 rows; hi 16K, lo 16K)
    {
        uint32_t d = smb + VO + vdsw;
        #pragma unroll
        for (int rho = 0; rho < 4; rho++) {
            cp16(d + rho * 4096, vsh + rho * 4096);
            cp16(d + 16384 + rho * 4096, vsl + rho * 4096);
        }
        cp_commit();
    }
    // adj prefetch (j=0, kk=0)
    int2 ajn[8];
    {
        int c0 = kh * 32 + cb;
        #pragma unroll
        for (int p = 0; p < 4; p++) {
            ajn[2 * p]     = *(const int2*)(adjB + (size_t)p * 8 * N_ + c0);
            ajn[2 * p + 1] = *(const int2*)(adjB + (size_t)p * 8 * N_ + c0 + 8);
        }
    }

    float C0[8][4], C1[8][4];
    #pragma unroll
    for (int f = 0; f < 8; f++)
        #pragma unroll
        for (int i = 0; i < 4; i++) { C0[f][i] = 0.f; C1[f][i] = 0.f; }
    float dden[4] = {0.f, 0.f, 0.f, 0.f};

    for (int j = 0; j < 32; j++) {
        if (j < 31) {
            // fill next buffer, then wait for current (1 group in flight)
            uint32_t d = smb + VO + (uint32_t)(((j + 1) & 1) * 32768) + vdsw;
            const char* sh = vsh + (size_t)(j + 1) * 16384;
            const char* sl = vsl + (size_t)(j + 1) * 16384;
            #pragma unroll
            for (int rho = 0; rho < 4; rho++) {
                cp16(d + rho * 4096, sh + rho * 4096);
                cp16(d + 16384 + rho * 4096, sl + rho * 4096);
            }
            cp_commit();
            cp_wait<1>();
        } else {
            cp_wait<0>();
        }
        __syncthreads();

        uint32_t vbhi = smb + VO + (uint32_t)((j & 1) * 32768);
        uint32_t vblo = vbhi + 16384;
        int sj = j * 128 + kh * 32;

        #pragma unroll
        for (int kk = 0; kk < 2; kk++) {
            int c0 = sj + kk * 16 + cb;
            float2 e1a = *(const float2*)&EB1s[c0];
            float2 e1b = *(const float2*)&EB1s[c0 + 8];
            float2 e2a = *(const float2*)&EB2s[c0];
            float2 e2b = *(const float2*)&EB2s[c0 + 8];

            uint32_t hA[4], hB[4], lA[4], lB[4];
            #pragma unroll
            for (int p = 0; p < 4; p++) {
                int2 A0 = ajn[2 * p], A1 = ajn[2 * p + 1];
                float p1, p2, x0, x1, x2, x3;
                p1 = ea1[p] * e1a.x; p2 = ea2[p] * e2a.x; x0 = (p1 > 1.f) ? p1 : p2; x0 = (A0.x > 0) ? x0 : 0.f;
                p1 = ea1[p] * e1a.y; p2 = ea2[p] * e2a.y; x1 = (p1 > 1.f) ? p1 : p2; x1 = (A0.y > 0) ? x1 : 0.f;
                p1 = ea1[p] * e1b.x; p2 = ea2[p] * e2b.x; x2 = (p1 > 1.f) ? p1 : p2; x2 = (A1.x > 0) ? x2 : 0.f;
                p1 = ea1[p] * e1b.y; p2 = ea2[p] * e2b.y; x3 = (p1 > 1.f) ? p1 : p2; x3 = (A1.y > 0) ? x3 : 0.f;
                dden[p] += (x0 + x1) + (x2 + x3);
                hA[p] = pack_hi(x0, x1);
                lA[p] = pack_rn(x0 - trunc_bf16(x0), x1 - trunc_bf16(x1));
                hB[p] = pack_hi(x2, x3);
                lB[p] = pack_rn(x2 - trunc_bf16(x2), x3 - trunc_bf16(x3));
            }
            // prefetch adj for next kk (or next super-block)
            {
                int cn = (kk < 1) ? (c0 + 16) : ((j < 31) ? (c0 + 112) : c0);
                #pragma unroll
                for (int p = 0; p < 4; p++) {
                    ajn[2 * p]     = *(const int2*)(adjB + (size_t)p * 8 * N_ + cn);
                    ajn[2 * p + 1] = *(const int2*)(adjB + (size_t)p * 8 * N_ + cn + 8);
                }
            }
            uint32_t ob = lb + (uint32_t)(kk * 2048);
            #pragma unroll
            for (int ng = 0; ng < 4; ng++) {
                uint32_t off = (ob + (uint32_t)(ng * 32)) ^ swx;
                uint32_t bh[4], bl[4];
                ldsm4t(bh, vbhi + off);
                ldsm4t(bl, vblo + off);
                mma16816(C0[2 * ng],     hA[0], hA[1], hB[0], hB[1], bh[0], bh[1]);
                mma16816(C1[2 * ng],     hA[2], hA[3], hB[2], hB[3], bh[0], bh[1]);
                mma16816(C0[2 * ng + 1], hA[0], hA[1], hB[0], hB[1], bh[2], bh[3]);
                mma16816(C1[2 * ng + 1], hA[2], hA[3], hB[2], hB[3], bh[2], bh[3]);
                mma16816(C0[2 * ng],     lA[0], lA[1], lB[0], lB[1], bh[0], bh[1]);
                mma16816(C1[2 * ng],     lA[2], lA[3], lB[2], lB[3], bh[0], bh[1]);
                mma16816(C0[2 * ng + 1], lA[0], lA[1], lB[0], lB[1], bh[2], bh[3]);
                mma16816(C1[2 * ng + 1], lA[2], lA[3], lB[2], lB[3], bh[2], bh[3]);
                mma16816(C0[2 * ng],     hA[0], hA[1], hB[0], hB[1], bl[0], bl[1]);
                mma16816(C1[2 * ng],     hA[2], hA[3], hB[2], hB[3], bl[0], bl[1]);
                mma16816(C0[2 * ng + 1], hA[0], hA[1], hB[0], hB[1], bl[2], bl[3]);
                mma16816(C1[2 * ng + 1], hA[2], hA[3], hB[2], hB[3], bl[2], bl[3]);
            }
        }
        __syncthreads();
    }

    // ---- epilogue ----
    #pragma unroll
    for (int p = 0; p < 4; p++) {
        dden[p] += __shfl_xor_sync(0xffffffffu, dden[p], 1);
        dden[p] += __shfl_xor_sync(0xffffffffu, dden[p], 2);
    }
    if ((l & 3) == 0) {
        #pragma unroll
        for (int p = 0; p < 4; p++) sden[kh * 64 + r0 + p * 8] = dden[p];
    }
    // kh=1..3 dump partials into V area: [kh-1][row(64)][64] floats
    if (kh) {
        float* mb = (float*)(sm + VO) + (size_t)(kh - 1) * 4096;
        #pragma unroll
        for (int g = 0; g < 2; g++) {
            int rr = wm * 32 + g * 16 + (l >> 2);
            float (*Cg)[4] = g ? C1 : C0;
            #pragma unroll
            for (int f = 0; f < 8; f++) {
                *(float2*)&mb[rr * 64 + f * 8 + cb]       = make_float2(Cg[f][0], Cg[f][1]);
                *(float2*)&mb[(rr + 8) * 64 + f * 8 + cb] = make_float2(Cg[f][2], Cg[f][3]);
            }
        }
    }
    __syncthreads();
    if (kh == 0) {
        const float* m1 = (const float*)(sm + VO);
        const float* m2 = m1 + 4096;
        const float* m3 = m2 + 4096;
        #pragma unroll
        for (int g = 0; g < 2; g++) {
            int rr = wm * 32 + g * 16 + (l >> 2);
            float rd0 = 1.f / (sden[rr] + sden[64 + rr] + sden[128 + rr] + sden[192 + rr]);
            int rs = rr + 8;
            float rd1 = 1.f / (sden[rs] + sden[64 + rs] + sden[128 + rs] + sden[192 + rs]);
            float (*Cg)[4] = g ? C1 : C0;
            float* o0 = out + (size_t)(bN + t0 + rr) * FO_ + cb;
            float* o1 = out + (size_t)(bN + t0 + rs) * FO_ + cb;
            #pragma unroll
            for (int f = 0; f < 8; f++) {
                int i0 = rr * 64 + f * 8 + cb, i1 = rs * 64 + f * 8 + cb;
                float x0 = (Cg[f][0] + m1[i0] + m2[i0] + m3[i0]) * rd0;
                float x1 = (Cg[f][1] + m1[i0 + 1] + m2[i0 + 1] + m3[i0 + 1]) * rd0;
                float x2 = (Cg[f][2] + m1[i1] + m2[i1] + m3[i1]) * rd1;
                float x3 = (Cg[f][3] + m1[i1 + 1] + m2[i1 + 1] + m3[i1 + 1]) * rd1;
                x0 = (x0 > 0.f) ? x0 : 0.01f * x0;
                x1 = (x1 > 0.f) ? x1 : 0.01f * x1;
                x2 = (x2 > 0.f) ? x2 : 0.01f * x2;
                x3 = (x3 > 0.f) ? x3 : 0.01f * x3;
                *(float2*)o0 = make_float2(x0, x1);
                *(float2*)o1 = make_float2(x2, x3);
                o0 += 8; o1 += 8;
            }
        }
    }
}

// ---------------- launcher ----------------
extern "C" void kernel_launch(void* const* d_in, const int* in_sizes, int n_in,
                              void* d_out, int out_size) {
    const float* h   = (const float*)d_in[0];
    const float* ctx = (const float*)d_in[1];
    const int*   adj = (const int*)d_in[2];
    const float* Ws  = (const float*)d_in[3];
    const float* Wt  = (const float*)d_in[4];
    const float* a   = (const float*)d_in[5];
    float* out = (float*)d_out;

    cudaFuncSetAttribute(gat_k2, cudaFuncAttributeMaxDynamicSharedMemorySize, K2_SMEM);
    cudaFuncSetAttribute(gat_main, cudaFuncAttributeMaxDynamicSharedMemorySize, SMEM_MAIN);

    gat_k2<<<(B_ * N_) / 64, 256, K2_SMEM>>>(ctx, Ws, a);
    gat_k3<<<(B_ * N_) / 64, 256>>>(h, Wt, a);
    gat_main<<<B_ * (N_ / TM_), 256, SMEM_MAIN>>>(adj, out);
}